// round 9
// baseline (speedup 1.0000x reference)
#include <cuda_runtime.h>

#define BB 32
#define NN 2048
#define HH 512
#define NCH 16           // n-chunks per batch
#define NPC (NN/NCH)     // 128 rows per chunk
#define RPW (NPC/16)     // rows per warp in k_alpha = 8
#define TO 4             // o-rows per k_out block

// ---- scratch (device globals; no allocation allowed) ----
__device__ float  g_p[BB*NN];              // unnormalized exp weights
__device__ float2 g_w01[BB*NN];            // premixed (p*sm, p*(1-sm))
__device__ float  g_psum[BB*NCH];          // partial sums of p
__device__ float  g_upart[BB*NCH*2*HH];    // partial weighted-V sums
__device__ float  g_u[BB*2*HH];            // normalized u0|u1

__device__ __forceinline__ float warp_sum(float v) {
#pragma unroll
    for (int o = 16; o; o >>= 1) v += __shfl_xor_sync(0xffffffffu, v, o);
    return v;
}

// ---------------- k_alpha: pure K stream ----------------
// grid (NCH, BB), 512 threads. Per warp: 8 rows, front-batched LDG.128,
// reductions batched at the end (round-8 phase 1, now phase-homogeneous).
// No max-subtraction needed: alpha ~ N(0,~0.8) => max over 64k ~ 3.5; exp safe.
__global__ void __launch_bounds__(512, 2)
k_alpha(const float* __restrict__ Q,
        const float* __restrict__ K,
        const float* __restrict__ w_att,
        const float* __restrict__ b_att,
        const int*   __restrict__ adj,
        const int*   __restrict__ s_mask) {
    __shared__ float sred[16];
    __shared__ float s_qd;

    int b = blockIdx.y, c = blockIdx.x;
    int n0 = c * NPC;
    int t = threadIdx.x;
    int w = t >> 5, l = t & 31;

    // qdot for this b (amortized over 256KB of streaming)
    float qv = Q[b * HH + t] * w_att[t];
    qv = warp_sum(qv);
    if (l == 0) sred[w] = qv;
    __syncthreads();
    if (t == 0) {
        float s = 0.f;
#pragma unroll
        for (int i = 0; i < 16; i++) s += sred[i];
        s_qd = s + b_att[0];
    }
    __syncthreads();
    float qd = s_qd;

    // wk in registers (uniform across warps, L1-served)
    const float4* wk4 = (const float4*)(w_att + HH);
    float4 wv0 = wk4[l], wv1 = wk4[32 + l], wv2 = wk4[64 + l], wv3 = wk4[96 + l];

    float sacc[RPW];
    const float4* kbase = (const float4*)(K + ((size_t)b * NN + n0 + w * RPW) * HH);
#pragma unroll
    for (int j = 0; j < RPW; j++) {
        const float4* kp = kbase + (size_t)j * (HH / 4);
        float4 k0 = kp[l], k1 = kp[32 + l], k2 = kp[64 + l], k3 = kp[96 + l];
        float s;
        s  = k0.x * wv0.x + k0.y * wv0.y + k0.z * wv0.z + k0.w * wv0.w;
        s += k1.x * wv1.x + k1.y * wv1.y + k1.z * wv1.z + k1.w * wv1.w;
        s += k2.x * wv2.x + k2.y * wv2.y + k2.z * wv2.z + k2.w * wv2.w;
        s += k3.x * wv3.x + k3.y * wv3.y + k3.z * wv3.z + k3.w * wv3.w;
        sacc[j] = s;
    }
    float pacc = 0.f;
#pragma unroll
    for (int j = 0; j < RPW; j++) {
        float s = warp_sum(sacc[j]);
        if (l == 0) {
            int gi = b * NN + n0 + w * RPW + j;
            float p = adj[gi] ? __expf(s + qd) : 0.f;
            int smv = s_mask[gi];
            g_w01[gi] = make_float2(smv ? p : 0.f, smv ? 0.f : p);
            g_p[gi] = p;
            pacc += p;
        }
    }
    // per-chunk psum
    if (l == 0) sred[w] = pacc;
    __syncthreads();
    if (w == 0) {
        float ps = (l < 16) ? sred[l] : 0.f;
        ps = warp_sum(ps);
        if (l == 0) g_psum[b * NCH + c] = ps;
    }
}

// ---------------- k_wv: pure V stream ----------------
// grid (NCH, BB), 512 threads. float4 loads, 4-way row split, smem reduce
// (round-8 phase 2, now phase-homogeneous; weights from g_w01).
__global__ void k_wv(const float* __restrict__ V) {
    __shared__ float sw0[NPC], sw1[NPC];
    __shared__ float4 red0[512], red1[512];

    int b = blockIdx.y, c = blockIdx.x;
    int n0 = c * NPC;
    int t = threadIdx.x;

    if (t < NPC) {
        float2 v = g_w01[b * NN + n0 + t];
        sw0[t] = v.x;
        sw1[t] = v.y;
    }
    __syncthreads();

    int h4 = t & 127;                                  // float4 column 0..127
    int rg = t >> 7;                                   // row group 0..3
    const float4* vp = (const float4*)V + ((size_t)b * NN + n0 + rg * (NPC / 4)) * (HH / 4) + h4;
    float4 a0 = make_float4(0.f, 0.f, 0.f, 0.f);
    float4 a1 = make_float4(0.f, 0.f, 0.f, 0.f);
#pragma unroll 8
    for (int i = 0; i < NPC / 4; i++) {               // 32 rows
        float4 v = __ldg(vp + (size_t)i * (HH / 4));
        float x0 = sw0[rg * (NPC / 4) + i];
        float x1 = sw1[rg * (NPC / 4) + i];
        a0.x += x0 * v.x; a0.y += x0 * v.y; a0.z += x0 * v.z; a0.w += x0 * v.w;
        a1.x += x1 * v.x; a1.y += x1 * v.y; a1.z += x1 * v.z; a1.w += x1 * v.w;
    }
    red0[t] = a0;
    red1[t] = a1;
    __syncthreads();
    if (t < 128) {
        float4 r0 = red0[t], r1 = red1[t];
#pragma unroll
        for (int g = 1; g < 4; g++) {
            float4 x = red0[t + g * 128];
            r0.x += x.x; r0.y += x.y; r0.z += x.z; r0.w += x.w;
            float4 y = red1[t + g * 128];
            r1.x += y.x; r1.y += y.y; r1.z += y.z; r1.w += y.w;
        }
        float4* up0 = (float4*)(g_upart + ((size_t)(b * NCH + c) * 2 + 0) * HH);
        float4* up1 = (float4*)(g_upart + ((size_t)(b * NCH + c) * 2 + 1) * HH);
        up0[t] = r0;
        up1[t] = r1;
    }
}

// ---------------- normalize: u = sum(upart)/sum(p); attn = p/sum(p) ----------------
// grid (8 slices, BB), 256 threads (round-8 version, measured good).
__global__ void __launch_bounds__(256)
k_norm(float* __restrict__ out) {
    __shared__ float sinv;
    int sl = blockIdx.x, b = blockIdx.y;
    int t = threadIdx.x, l = t & 31;

    if (t < 32) {
        float ps = (l < NCH) ? g_psum[b * NCH + l] : 0.f;
        ps = warp_sum(ps);
        if (l == 0) sinv = 1.0f / ps;
    }
    __syncthreads();
    float inv = sinv;

    int ai = sl * 256 + t;
    out[b * NN + ai] = g_p[b * NN + ai] * inv;

    if (sl < 4) {
        int ui = sl * 256 + t;
        float s = 0.f;
#pragma unroll
        for (int cc = 0; cc < NCH; cc++)
            s += g_upart[(size_t)(b * NCH + cc) * 2 * HH + ui];
        g_u[b * 2 * HH + ui] = s * inv;
    }
}

// ---------------- epilogue: attn_sum[b,o] = u0·Wr0[o] + u1·Wr1[o] + Q[b]·Wri[o] ----------------
// grid (128 o-tiles, 2 b-halves), 256 threads; weights in smem (round-8 version).
__global__ void __launch_bounds__(256)
k_out(const float* __restrict__ Q,
      const float* __restrict__ Wr0,
      const float* __restrict__ Wr1,
      const float* __restrict__ Wri,
      float* __restrict__ out) {
    __shared__ float s_w[3][TO][HH];
    int o0 = blockIdx.x * TO;
    int bh = blockIdx.y;
    int t = threadIdx.x, w = t >> 5, l = t & 31;

    const float4* w0g = (const float4*)(Wr0 + (size_t)o0 * HH);
    const float4* w1g = (const float4*)(Wr1 + (size_t)o0 * HH);
    const float4* wig = (const float4*)(Wri + (size_t)o0 * HH);
#pragma unroll
    for (int i = 0; i < (TO * HH / 4) / 256; i++) {
        int idx = i * 256 + t;
        ((float4*)&s_w[0][0][0])[idx] = w0g[idx];
        ((float4*)&s_w[1][0][0])[idx] = w1g[idx];
        ((float4*)&s_w[2][0][0])[idx] = wig[idx];
    }
    __syncthreads();

#pragma unroll
    for (int bb = 0; bb < 2; bb++) {
        int b = bh * 16 + bb * 8 + w;
        const float4* u0 = (const float4*)(g_u + b * 2 * HH);
        const float4* u1 = u0 + HH / 4;
        const float4* q  = (const float4*)(Q + b * HH);
        float4 u0f[4], u1f[4], qf[4];
#pragma unroll
        for (int i = 0; i < 4; i++) {
            u0f[i] = u0[i * 32 + l];
            u1f[i] = u1[i * 32 + l];
            qf[i]  = q[i * 32 + l];
        }
#pragma unroll
        for (int o = 0; o < TO; o++) {
            const float4* sw0p = (const float4*)&s_w[0][o][0];
            const float4* sw1p = (const float4*)&s_w[1][o][0];
            const float4* swip = (const float4*)&s_w[2][o][0];
            float s = 0.f;
#pragma unroll
            for (int i = 0; i < 4; i++) {
                int idx = i * 32 + l;
                float4 x;
                x = sw0p[idx];
                s += u0f[i].x * x.x + u0f[i].y * x.y + u0f[i].z * x.z + u0f[i].w * x.w;
                x = sw1p[idx];
                s += u1f[i].x * x.x + u1f[i].y * x.y + u1f[i].z * x.z + u1f[i].w * x.w;
                x = swip[idx];
                s += qf[i].x * x.x + qf[i].y * x.y + qf[i].z * x.z + qf[i].w * x.w;
            }
            s = warp_sum(s);
            if (l == 0) out[BB * NN + b * HH + o0 + o] = s;
        }
    }
}

// ---------------- launch ----------------
extern "C" void kernel_launch(void* const* d_in, const int* in_sizes, int n_in,
                              void* d_out, int out_size) {
    const float* Q     = (const float*)d_in[0];
    const float* K     = (const float*)d_in[1];
    const float* V     = (const float*)d_in[2];
    const int*   adj   = (const int*)d_in[3];
    const int*   smask = (const int*)d_in[4];
    const float* w_att = (const float*)d_in[5];
    const float* b_att = (const float*)d_in[6];
    const float* Wr0   = (const float*)d_in[7];
    const float* Wr1   = (const float*)d_in[8];
    const float* Wri   = (const float*)d_in[9];
    float* out = (float*)d_out;

    k_alpha<<<dim3(NCH, BB), 512>>>(Q, K, w_att, b_att, adj, smask);
    k_wv<<<dim3(NCH, BB), 512>>>(V);
    k_norm<<<dim3(8, BB), 256>>>(out);
    k_out<<<dim3(HH / TO, 2), 256>>>(Q, Wr0, Wr1, Wri, out);
}

// round 10
// speedup vs baseline: 1.0667x; 1.0667x over previous
#include <cuda_runtime.h>

#define BB 32
#define NN 2048
#define HH 512
#define NCH 16           // n-chunks per batch for the fused pass
#define NPC (NN/NCH)     // 128 rows per chunk
#define RPW (NPC/16)     // rows per warp in phase 1 = 8

// ---- scratch (device globals; no allocation allowed) ----
__device__ float g_p[BB*NN];              // unnormalized exp weights
__device__ float g_psum[BB*NCH];          // partial sums of p
__device__ float g_upart[BB*NCH*2*HH];    // partial weighted-V sums
__device__ float g_u[BB*2*HH];            // normalized u0|u1

__device__ __forceinline__ float warp_sum(float v) {
#pragma unroll
    for (int o = 16; o; o >>= 1) v += __shfl_xor_sync(0xffffffffu, v, o);
    return v;
}

// ---------------- fused: qdot, alpha -> p = adj*exp(alpha), weighted V partials ----------------
// ROUND-8 VERSION VERBATIM (measured 46.0us @ 75.3% DRAM).
// No max-subtraction needed: alpha ~ N(0,~0.8) => max over 64k ~ 3.5; exp safe.
__global__ void __launch_bounds__(512, 2)
k_fused(const float* __restrict__ Q,
        const float* __restrict__ K,
        const float* __restrict__ V,
        const float* __restrict__ w_att,
        const float* __restrict__ b_att,
        const int*   __restrict__ adj,
        const int*   __restrict__ s_mask) {
    __shared__ float wk[HH];
    __shared__ float sw0[NPC], sw1[NPC];
    __shared__ float sred[16];
    __shared__ float s_qd;
    __shared__ float4 red0[512], red1[512];

    int b = blockIdx.y, c = blockIdx.x;
    int n0 = c * NPC;
    int t = threadIdx.x;
    int w = t >> 5, l = t & 31;

    wk[t] = w_att[HH + t];

    // ---- phase 0: qdot for this b ----
    float qv = Q[b * HH + t] * w_att[t];
    qv = warp_sum(qv);
    if (l == 0) sred[w] = qv;
    __syncthreads();
    if (t == 0) {
        float s = 0.f;
#pragma unroll
        for (int i = 0; i < 16; i++) s += sred[i];
        s_qd = s + b_att[0];
    }
    __syncthreads();
    float qd = s_qd;

    // ---- phase 1: p for 128 rows (16 warps x 8 rows, batched loads then batched reductions) ----
    const float4* wk4 = (const float4*)wk;
    float4 wv0 = wk4[l], wv1 = wk4[32 + l], wv2 = wk4[64 + l], wv3 = wk4[96 + l];

    float sacc[RPW];
    const float4* kbase = (const float4*)(K + ((size_t)b * NN + n0 + w * RPW) * HH);
#pragma unroll
    for (int j = 0; j < RPW; j++) {
        const float4* kp = kbase + (size_t)j * (HH / 4);
        float4 k0 = kp[l], k1 = kp[32 + l], k2 = kp[64 + l], k3 = kp[96 + l];
        float s;
        s  = k0.x * wv0.x + k0.y * wv0.y + k0.z * wv0.z + k0.w * wv0.w;
        s += k1.x * wv1.x + k1.y * wv1.y + k1.z * wv1.z + k1.w * wv1.w;
        s += k2.x * wv2.x + k2.y * wv2.y + k2.z * wv2.z + k2.w * wv2.w;
        s += k3.x * wv3.x + k3.y * wv3.y + k3.z * wv3.z + k3.w * wv3.w;
        sacc[j] = s;
    }
#pragma unroll
    for (int j = 0; j < RPW; j++) {
        float s = warp_sum(sacc[j]);
        if (l == 0) {
            int r = w * RPW + j;
            int gi = b * NN + n0 + r;
            float p = adj[gi] ? __expf(s + qd) : 0.f;
            int smv = s_mask[gi];
            sw0[r] = smv ? p : 0.f;
            sw1[r] = smv ? 0.f : p;
            g_p[gi] = p;
        }
    }
    __syncthreads();

    // partial psum (warp 0; overlaps with start of phase 2 on other warps)
    if (w == 0) {
        float ps = 0.f;
#pragma unroll
        for (int i = 0; i < NPC / 32; i++) ps += sw0[i * 32 + l] + sw1[i * 32 + l];
        ps = warp_sum(ps);
        if (l == 0) g_psum[b * NCH + c] = ps;
    }

    // ---- phase 2: weighted V accumulation (float4, 4-way row split) ----
    int h4 = t & 127;                                  // float4 column 0..127
    int rg = t >> 7;                                   // row group 0..3
    const float4* vp = (const float4*)V + ((size_t)b * NN + n0 + rg * (NPC / 4)) * (HH / 4) + h4;
    float4 a0 = make_float4(0.f, 0.f, 0.f, 0.f);
    float4 a1 = make_float4(0.f, 0.f, 0.f, 0.f);
#pragma unroll 8
    for (int i = 0; i < NPC / 4; i++) {               // 32 rows
        float4 v = __ldg(vp + (size_t)i * (HH / 4));
        float x0 = sw0[rg * (NPC / 4) + i];
        float x1 = sw1[rg * (NPC / 4) + i];
        a0.x += x0 * v.x; a0.y += x0 * v.y; a0.z += x0 * v.z; a0.w += x0 * v.w;
        a1.x += x1 * v.x; a1.y += x1 * v.y; a1.z += x1 * v.z; a1.w += x1 * v.w;
    }
    red0[t] = a0;
    red1[t] = a1;
    __syncthreads();
    if (t < 128) {
        float4 r0 = red0[t], r1 = red1[t];
#pragma unroll
        for (int g = 1; g < 4; g++) {
            float4 x = red0[t + g * 128];
            r0.x += x.x; r0.y += x.y; r0.z += x.z; r0.w += x.w;
            float4 y = red1[t + g * 128];
            r1.x += y.x; r1.y += y.y; r1.z += y.z; r1.w += y.w;
        }
        float4* up0 = (float4*)(g_upart + ((size_t)(b * NCH + c) * 2 + 0) * HH);
        float4* up1 = (float4*)(g_upart + ((size_t)(b * NCH + c) * 2 + 1) * HH);
        up0[t] = r0;
        up1[t] = r1;
    }
}

// ---------------- normalize: u = sum(upart)/sum(p); attn = p/sum(p) ----------------
// grid (8 slices, BB), 256 threads (round-8 version, measured good).
__global__ void __launch_bounds__(256)
k_norm(float* __restrict__ out) {
    __shared__ float sinv;
    int sl = blockIdx.x, b = blockIdx.y;
    int t = threadIdx.x, l = t & 31;

    if (t < 32) {
        float ps = (l < NCH) ? g_psum[b * NCH + l] : 0.f;
        ps = warp_sum(ps);
        if (l == 0) sinv = 1.0f / ps;
    }
    __syncthreads();
    float inv = sinv;

    int ai = sl * 256 + t;
    out[b * NN + ai] = g_p[b * NN + ai] * inv;

    if (sl < 4) {
        int ui = sl * 256 + t;
        float s = 0.f;
#pragma unroll
        for (int cc = 0; cc < NCH; cc++)
            s += g_upart[(size_t)(b * NCH + cc) * 2 * HH + ui];
        g_u[b * 2 * HH + ui] = s * inv;
    }
}

// ---------------- epilogue: attn_sum[b,o] = u0·Wr0[o] + u1·Wr1[o] + Q[b]·Wri[o] ----------------
// One warp per (o, 4-b group): weight float4s loaded once, reused across 4 b's
// (u/Q are 320KB total -> L1-resident). grid (64, 8) = 512 blocks, 8 warps each.
// Low registers (no cross-iteration caching), high occupancy.
__global__ void __launch_bounds__(256)
k_out(const float* __restrict__ Q,
      const float* __restrict__ Wr0,
      const float* __restrict__ Wr1,
      const float* __restrict__ Wri,
      float* __restrict__ out) {
    int t = threadIdx.x, w = t >> 5, l = t & 31;
    int o  = blockIdx.x * 8 + w;
    int b0 = blockIdx.y * 4;

    const float4* w0g = (const float4*)(Wr0 + (size_t)o * HH);
    const float4* w1g = (const float4*)(Wr1 + (size_t)o * HH);
    const float4* wig = (const float4*)(Wri + (size_t)o * HH);

    float acc0 = 0.f, acc1 = 0.f, acc2 = 0.f, acc3 = 0.f;
#pragma unroll
    for (int i = 0; i < 4; i++) {                     // 128 float4 / 32 lanes
        int idx = i * 32 + l;
        float4 w0 = w0g[idx];
        float4 w1 = w1g[idx];
        float4 wi = wig[idx];
#pragma unroll
        for (int bb = 0; bb < 4; bb++) {
            int b = b0 + bb;
            float4 u0 = ((const float4*)(g_u + b * 2 * HH))[idx];
            float4 u1 = ((const float4*)(g_u + b * 2 * HH + HH))[idx];
            float4 qv = ((const float4*)(Q + b * HH))[idx];
            float s;
            s  = u0.x * w0.x + u0.y * w0.y + u0.z * w0.z + u0.w * w0.w;
            s += u1.x * w1.x + u1.y * w1.y + u1.z * w1.z + u1.w * w1.w;
            s += qv.x * wi.x + qv.y * wi.y + qv.z * wi.z + qv.w * wi.w;
            if (bb == 0) acc0 += s;
            else if (bb == 1) acc1 += s;
            else if (bb == 2) acc2 += s;
            else acc3 += s;
        }
    }
    acc0 = warp_sum(acc0);
    acc1 = warp_sum(acc1);
    acc2 = warp_sum(acc2);
    acc3 = warp_sum(acc3);
    if (l == 0) {
        out[BB * NN + (b0 + 0) * HH + o] = acc0;
        out[BB * NN + (b0 + 1) * HH + o] = acc1;
        out[BB * NN + (b0 + 2) * HH + o] = acc2;
        out[BB * NN + (b0 + 3) * HH + o] = acc3;
    }
}

// ---------------- launch ----------------
extern "C" void kernel_launch(void* const* d_in, const int* in_sizes, int n_in,
                              void* d_out, int out_size) {
    const float* Q     = (const float*)d_in[0];
    const float* K     = (const float*)d_in[1];
    const float* V     = (const float*)d_in[2];
    const int*   adj   = (const int*)d_in[3];
    const int*   smask = (const int*)d_in[4];
    const float* w_att = (const float*)d_in[5];
    const float* b_att = (const float*)d_in[6];
    const float* Wr0   = (const float*)d_in[7];
    const float* Wr1   = (const float*)d_in[8];
    const float* Wri   = (const float*)d_in[9];
    float* out = (float*)d_out;

    k_fused<<<dim3(NCH, BB), 512>>>(Q, K, V, w_att, b_att, adj, smask);
    k_norm<<<dim3(8, BB), 256>>>(out);
    k_out<<<dim3(64, 8), 256>>>(Q, Wr0, Wr1, Wri, out);
}

// round 11
// speedup vs baseline: 1.0708x; 1.0039x over previous
#include <cuda_runtime.h>

#define BB 32
#define NN 2048
#define HH 512
#define NCH 16           // n-chunks per batch for the fused pass
#define NPC (NN/NCH)     // 128 rows per chunk
#define RPW (NPC/16)     // rows per warp in phase 1 = 8

// ---- scratch (device globals; no allocation allowed) ----
__device__ float g_p[BB*NN];              // unnormalized exp weights
__device__ float g_psum[BB*NCH];          // partial sums of p
__device__ float g_upart[BB*NCH*2*HH];    // partial weighted-V sums
__device__ float g_u[BB*2*HH];            // normalized u0|u1

__device__ __forceinline__ float warp_sum(float v) {
#pragma unroll
    for (int o = 16; o; o >>= 1) v += __shfl_xor_sync(0xffffffffu, v, o);
    return v;
}

// ---------------- fused: qdot, alpha -> p = adj*exp(alpha), weighted V partials ----------------
// ROUND-8 VERSION VERBATIM (measured 45.3-46.0us @ ~76% DRAM). PROTECTED.
// No max-subtraction needed: alpha ~ N(0,~0.8) => max over 64k ~ 3.5; exp safe.
__global__ void __launch_bounds__(512, 2)
k_fused(const float* __restrict__ Q,
        const float* __restrict__ K,
        const float* __restrict__ V,
        const float* __restrict__ w_att,
        const float* __restrict__ b_att,
        const int*   __restrict__ adj,
        const int*   __restrict__ s_mask) {
    __shared__ float wk[HH];
    __shared__ float sw0[NPC], sw1[NPC];
    __shared__ float sred[16];
    __shared__ float s_qd;
    __shared__ float4 red0[512], red1[512];

    int b = blockIdx.y, c = blockIdx.x;
    int n0 = c * NPC;
    int t = threadIdx.x;
    int w = t >> 5, l = t & 31;

    wk[t] = w_att[HH + t];

    // ---- phase 0: qdot for this b ----
    float qv = Q[b * HH + t] * w_att[t];
    qv = warp_sum(qv);
    if (l == 0) sred[w] = qv;
    __syncthreads();
    if (t == 0) {
        float s = 0.f;
#pragma unroll
        for (int i = 0; i < 16; i++) s += sred[i];
        s_qd = s + b_att[0];
    }
    __syncthreads();
    float qd = s_qd;

    // ---- phase 1: p for 128 rows (16 warps x 8 rows, batched loads then batched reductions) ----
    const float4* wk4 = (const float4*)wk;
    float4 wv0 = wk4[l], wv1 = wk4[32 + l], wv2 = wk4[64 + l], wv3 = wk4[96 + l];

    float sacc[RPW];
    const float4* kbase = (const float4*)(K + ((size_t)b * NN + n0 + w * RPW) * HH);
#pragma unroll
    for (int j = 0; j < RPW; j++) {
        const float4* kp = kbase + (size_t)j * (HH / 4);
        float4 k0 = kp[l], k1 = kp[32 + l], k2 = kp[64 + l], k3 = kp[96 + l];
        float s;
        s  = k0.x * wv0.x + k0.y * wv0.y + k0.z * wv0.z + k0.w * wv0.w;
        s += k1.x * wv1.x + k1.y * wv1.y + k1.z * wv1.z + k1.w * wv1.w;
        s += k2.x * wv2.x + k2.y * wv2.y + k2.z * wv2.z + k2.w * wv2.w;
        s += k3.x * wv3.x + k3.y * wv3.y + k3.z * wv3.z + k3.w * wv3.w;
        sacc[j] = s;
    }
#pragma unroll
    for (int j = 0; j < RPW; j++) {
        float s = warp_sum(sacc[j]);
        if (l == 0) {
            int r = w * RPW + j;
            int gi = b * NN + n0 + r;
            float p = adj[gi] ? __expf(s + qd) : 0.f;
            int smv = s_mask[gi];
            sw0[r] = smv ? p : 0.f;
            sw1[r] = smv ? 0.f : p;
            g_p[gi] = p;
        }
    }
    __syncthreads();

    // partial psum (warp 0; overlaps with start of phase 2 on other warps)
    if (w == 0) {
        float ps = 0.f;
#pragma unroll
        for (int i = 0; i < NPC / 32; i++) ps += sw0[i * 32 + l] + sw1[i * 32 + l];
        ps = warp_sum(ps);
        if (l == 0) g_psum[b * NCH + c] = ps;
    }

    // ---- phase 2: weighted V accumulation (float4, 4-way row split) ----
    int h4 = t & 127;                                  // float4 column 0..127
    int rg = t >> 7;                                   // row group 0..3
    const float4* vp = (const float4*)V + ((size_t)b * NN + n0 + rg * (NPC / 4)) * (HH / 4) + h4;
    float4 a0 = make_float4(0.f, 0.f, 0.f, 0.f);
    float4 a1 = make_float4(0.f, 0.f, 0.f, 0.f);
#pragma unroll 8
    for (int i = 0; i < NPC / 4; i++) {               // 32 rows
        float4 v = __ldg(vp + (size_t)i * (HH / 4));
        float x0 = sw0[rg * (NPC / 4) + i];
        float x1 = sw1[rg * (NPC / 4) + i];
        a0.x += x0 * v.x; a0.y += x0 * v.y; a0.z += x0 * v.z; a0.w += x0 * v.w;
        a1.x += x1 * v.x; a1.y += x1 * v.y; a1.z += x1 * v.z; a1.w += x1 * v.w;
    }
    red0[t] = a0;
    red1[t] = a1;
    __syncthreads();
    if (t < 128) {
        float4 r0 = red0[t], r1 = red1[t];
#pragma unroll
        for (int g = 1; g < 4; g++) {
            float4 x = red0[t + g * 128];
            r0.x += x.x; r0.y += x.y; r0.z += x.z; r0.w += x.w;
            float4 y = red1[t + g * 128];
            r1.x += y.x; r1.y += y.y; r1.z += y.z; r1.w += y.w;
        }
        float4* up0 = (float4*)(g_upart + ((size_t)(b * NCH + c) * 2 + 0) * HH);
        float4* up1 = (float4*)(g_upart + ((size_t)(b * NCH + c) * 2 + 1) * HH);
        up0[t] = r0;
        up1[t] = r1;
    }
}

// ---------------- normalize: u = sum(upart)/sum(p); attn = p/sum(p) ----------------
// grid (8 slices, BB), 256 threads (round-8 version verbatim). PROTECTED.
__global__ void __launch_bounds__(256)
k_norm(float* __restrict__ out) {
    __shared__ float sinv;
    int sl = blockIdx.x, b = blockIdx.y;
    int t = threadIdx.x, l = t & 31;

    if (t < 32) {
        float ps = (l < NCH) ? g_psum[b * NCH + l] : 0.f;
        ps = warp_sum(ps);
        if (l == 0) sinv = 1.0f / ps;
    }
    __syncthreads();
    float inv = sinv;

    int ai = sl * 256 + t;
    out[b * NN + ai] = g_p[b * NN + ai] * inv;

    if (sl < 4) {
        int ui = sl * 256 + t;
        float s = 0.f;
#pragma unroll
        for (int cc = 0; cc < NCH; cc++)
            s += g_upart[(size_t)(b * NCH + cc) * 2 * HH + ui];
        g_u[b * 2 * HH + ui] = s * inv;
    }
}

// ---------------- epilogue v3: attn_sum[b,o] = u0·Wr0[o] + u1·Wr1[o] + Q[b]·Wri[o] ----------------
// grid (64 o-tiles, 8 b-groups), 256 threads. u/Q for the 4-b group cached in
// smem (shared by all warps, conflict-free); weights front-batched into 48 regs
// (12 independent LDG.128 -> single latency exposure). Accumulation = regs + LDS only.
__global__ void __launch_bounds__(256)
k_out(const float* __restrict__ Q,
      const float* __restrict__ Wr0,
      const float* __restrict__ Wr1,
      const float* __restrict__ Wri,
      float* __restrict__ out) {
    __shared__ float4 s_u0[4][HH/4], s_u1[4][HH/4], s_q[4][HH/4];
    int t = threadIdx.x, w = t >> 5, l = t & 31;
    int o  = blockIdx.x * 8 + w;
    int b0 = blockIdx.y * 4;

    // cooperative operand load: 3 arrays x 512 float4 (2 per thread per array)
#pragma unroll
    for (int j = 0; j < 2; j++) {
        int idx = j * 256 + t;                 // 0..511
        int bb = idx >> 7, h4 = idx & 127;
        s_u0[bb][h4] = ((const float4*)(g_u + (size_t)(b0 + bb) * 2 * HH))[h4];
        s_u1[bb][h4] = ((const float4*)(g_u + (size_t)(b0 + bb) * 2 * HH + HH))[h4];
        s_q [bb][h4] = ((const float4*)(Q + (size_t)(b0 + bb) * HH))[h4];
    }

    // weights into registers (12 independent loads, front-batched)
    const float4* w0g = (const float4*)(Wr0 + (size_t)o * HH);
    const float4* w1g = (const float4*)(Wr1 + (size_t)o * HH);
    const float4* wig = (const float4*)(Wri + (size_t)o * HH);
    float4 w0f[4], w1f[4], wif[4];
#pragma unroll
    for (int i = 0; i < 4; i++) {
        int idx = i * 32 + l;
        w0f[i] = w0g[idx];
        w1f[i] = w1g[idx];
        wif[i] = wig[idx];
    }
    __syncthreads();

    float acc[4];
#pragma unroll
    for (int bb = 0; bb < 4; bb++) {
        float s = 0.f;
#pragma unroll
        for (int i = 0; i < 4; i++) {
            int idx = i * 32 + l;
            float4 u0 = s_u0[bb][idx];
            float4 u1 = s_u1[bb][idx];
            float4 qv = s_q[bb][idx];
            s += u0.x * w0f[i].x + u0.y * w0f[i].y + u0.z * w0f[i].z + u0.w * w0f[i].w;
            s += u1.x * w1f[i].x + u1.y * w1f[i].y + u1.z * w1f[i].z + u1.w * w1f[i].w;
            s += qv.x * wif[i].x + qv.y * wif[i].y + qv.z * wif[i].z + qv.w * wif[i].w;
        }
        acc[bb] = warp_sum(s);
    }
    if (l == 0) {
#pragma unroll
        for (int bb = 0; bb < 4; bb++)
            out[BB * NN + (size_t)(b0 + bb) * HH + o] = acc[bb];
    }
}

// ---------------- launch ----------------
extern "C" void kernel_launch(void* const* d_in, const int* in_sizes, int n_in,
                              void* d_out, int out_size) {
    const float* Q     = (const float*)d_in[0];
    const float* K     = (const float*)d_in[1];
    const float* V     = (const float*)d_in[2];
    const int*   adj   = (const int*)d_in[3];
    const int*   smask = (const int*)d_in[4];
    const float* w_att = (const float*)d_in[5];
    const float* b_att = (const float*)d_in[6];
    const float* Wr0   = (const float*)d_in[7];
    const float* Wr1   = (const float*)d_in[8];
    const float* Wri   = (const float*)d_in[9];
    float* out = (float*)d_out;

    k_fused<<<dim3(NCH, BB), 512>>>(Q, K, V, w_att, b_att, adj, smask);
    k_norm<<<dim3(8, BB), 256>>>(out);
    k_out<<<dim3(64, 8), 256>>>(Q, Wr0, Wr1, Wri, out);
}